// round 11
// baseline (speedup 1.0000x reference)
#include <cuda_runtime.h>

// 4D transposed conv, stride 2:
//   out[b,co,o1..o4] = bias[co] + sum_{ci,k1..k4 : o=2i+k} x[b,ci,i1..i4] * w[ci,co,k1..k4]
// Per (b,o1,o2) block: for each valid (k1,k2)->(i1,i2) combo,
//   GEMM C[(i3,i4),(co,k3,k4)] = sum_ci x[ci,i3,i4]*w[ci,co,k3,k4]   (fma.rn.f32x2)
//   scatter out_s[co][2*i3+k3][2*i4+k4] += C
// FFMA2 pair axis = adjacent co: w operand is a natural LDS.64 pair from w_s,
// x operand comes pre-duplicated (v,v) from x_s. Zero register packing in the
// mainloop. Warp w owns i3 row w; lane&15 -> co pair; lane>>4 -> i4 half.
// Seam fix: o4=12 is reachable from both i4-halves (ih=0:(h=5,k4=2),
// ih=1:(h=0,k4=0)). ih=1 shuffles that accumulator down to its ih=0 partner
// (same co pair), which folds it in pre-scatter; ih=1 skips the write.

#define NKW (81 * 64 * 64)
__device__ float g_wT[NKW];  // [k1,k2,k3,k4][ci][co]

__global__ void transpose_w_kernel(const float* __restrict__ w) {
    int idx = blockIdx.x * blockDim.x + threadIdx.x;
    if (idx < NKW) {
        int kidx = idx >> 12;        // 0..80
        int cico = idx & 4095;       // ci*64+co
        g_wT[idx] = w[cico * 81 + kidx];
    }
}

// smem (floats): out_s[32*625]=20000, w_s[9*64*32]=18432, x_s[64*144*2]=18432
#define WS_OFF 20000
#define XS_OFF 38432
#define SMEM_FLOATS 56864

typedef unsigned long long u64;

__device__ __forceinline__ void fma2(u64& d, u64 a, u64 b) {
    asm("fma.rn.f32x2 %0, %1, %2, %0;" : "+l"(d) : "l"(a), "l"(b));
}
__device__ __forceinline__ void add2(u64& d, u64 a) {
    asm("add.rn.f32x2 %0, %0, %1;" : "+l"(d) : "l"(a));
}
__device__ __forceinline__ void unpack2(u64 v, float& lo, float& hi) {
    unsigned int l, h;
    asm("mov.b64 {%0, %1}, %2;" : "=r"(l), "=r"(h) : "l"(v));
    lo = __uint_as_float(l);
    hi = __uint_as_float(h);
}

__global__ __launch_bounds__(384, 1) void deconv4d_kernel(
    const float* __restrict__ x, const float* __restrict__ bias,
    float* __restrict__ out)
{
    extern __shared__ float smem[];
    float* out_s = smem;               // [32 co][25 o3][25 o4]
    float* w_s   = smem + WS_OFF;      // [t9=k3*3+k4][ci][co(32)]
    float* x_s   = smem + XS_OFF;      // [ci][i3][i4][2]  (duplicated pairs)

    const int tid    = threadIdx.x;
    const int lane   = tid & 31;
    const int lane15 = lane & 15;      // -> co pair base (co = 2*lane15)
    const int ih     = lane >> 4;      // -> i4 half (i40 = ih*6)
    const int wid    = tid >> 5;       // -> i3 row (0..11)
    const int i40    = ih * 6;
    const int b  = blockIdx.y;
    const int o1 = blockIdx.x / 25;
    const int o2 = blockIdx.x % 25;

    // valid (k,i) pairs for dims 1 and 2
    int nk1 = 0, k1s[2], i1s[2];
    #pragma unroll
    for (int k = 0; k < 3; k++)
        if (k <= o1 && ((o1 - k) & 1) == 0 && ((o1 - k) >> 1) < 12) {
            k1s[nk1] = k; i1s[nk1] = (o1 - k) >> 1; nk1++;
        }
    int nk2 = 0, k2s[2], i2s[2];
    #pragma unroll
    for (int k = 0; k < 3; k++)
        if (k <= o2 && ((o2 - k) & 1) == 0 && ((o2 - k) >> 1) < 12) {
            k2s[nk2] = k; i2s[nk2] = (o2 - k) >> 1; nk2++;
        }

    for (int coh = 0; coh < 2; coh++) {
        const int co0 = coh * 32;

        // init accumulation buffer with bias
        for (int i = tid; i < 20000; i += 384)
            out_s[i] = bias[co0 + i / 625];
        __syncthreads();

        for (int c1 = 0; c1 < nk1; c1++) {
            for (int c2 = 0; c2 < nk2; c2++) {
                const int i1 = i1s[c1], i2 = i2s[c2];
                const int kbase = (k1s[c1] * 3 + k2s[c2]) * 9;

                // x slab, duplicated pairs: x_s[ci*288 + r*2 + {0,1}] = v
                for (int t = tid; t < 9216; t += 384) {
                    int ci = t / 144, r = t - ci * 144;
                    float v = x[((size_t)((b * 64 + ci) * 144 + i1 * 12 + i2))
                                * 144 + r];
                    ((float2*)x_s)[ci * 144 + r] = make_float2(v, v);
                }
                // w slab [9 taps][64 ci][32 co]
                for (int t = tid; t < 4608; t += 384) {
                    int c4 = t & 7, ci = (t >> 3) & 63, t9 = t >> 9;
                    ((float4*)w_s)[t] = *(const float4*)(g_wT +
                        (kbase + t9) * 4096 + ci * 64 + co0 + c4 * 4);
                }
                __syncthreads();

                // mainloop: thread tile = 6 i4 x 2 co x 9 taps (acc pairs co)
                u64 acc[54];
                #pragma unroll
                for (int i = 0; i < 54; i++) acc[i] = 0ULL;

                const float* xb = x_s + wid * 24 + i40 * 2;  // duplicated row seg
                const float* wb = w_s + 2 * lane15;
                for (int ci = 0; ci < 64; ci++) {
                    // 6 duplicated x pairs = 48B contiguous, 16B-aligned
                    const ulonglong2* xp = (const ulonglong2*)(xb + ci * 288);
                    ulonglong2 p0 = xp[0], p1 = xp[1], p2 = xp[2];
                    u64 xv0 = p0.x, xv1 = p0.y, xv2 = p1.x;
                    u64 xv3 = p1.y, xv4 = p2.x, xv5 = p2.y;
                    const u64* wr = (const u64*)(wb + ci * 32);
                    #pragma unroll
                    for (int t9 = 0; t9 < 9; t9++) {
                        u64 w2 = wr[t9 * 1024];   // [t9][ci][co pair], LDS.64
                        fma2(acc[t9 * 6 + 0], xv0, w2);
                        fma2(acc[t9 * 6 + 1], xv1, w2);
                        fma2(acc[t9 * 6 + 2], xv2, w2);
                        fma2(acc[t9 * 6 + 3], xv3, w2);
                        fma2(acc[t9 * 6 + 4], xv4, w2);
                        fma2(acc[t9 * 6 + 5], xv5, w2);
                    }
                }

                // seam transfer: ih=1's (k4=0,h=0) cell (o4=12) is the same as
                // ih=0's (k4=2,h=5) cell. Shuffle it to the ih=0 partner lane
                // (same co pair) and fold it in; ih=1 will skip that write.
                #pragma unroll
                for (int k3 = 0; k3 < 3; k3++) {
                    u64 v = __shfl_down_sync(0xFFFFFFFFu, acc[(k3 * 3) * 6], 16);
                    if (ih == 0) add2(acc[(k3 * 3 + 2) * 6 + 5], v);
                }

                // scatter, 2 conflict-free rounds (acc pair = co, co+1)
                float* osb = out_s + (2 * lane15) * 625;
                // Round A: k3 in {0,1} -> o3 in {2*wid, 2*wid+1}
                #pragma unroll
                for (int k3 = 0; k3 < 2; k3++) {
                    float* row0 = osb + (2 * wid + k3) * 25;
                    float* row1 = row0 + 625;
                    #pragma unroll
                    for (int k4 = 0; k4 < 3; k4++) {
                        const int t9 = k3 * 3 + k4;
                        #pragma unroll
                        for (int h = 0; h < 6; h++) {
                            if (k4 == 0 && h == 0 && ih != 0) continue;  // seam
                            float c0, c1;
                            unpack2(acc[t9 * 6 + h], c0, c1);
                            const int o4 = 2 * (i40 + h) + k4;
                            row0[o4] += c0;
                            row1[o4] += c1;
                        }
                    }
                }
                __syncthreads();
                // Round B: k3 = 2 -> o3 = 2*wid+2
                {
                    float* row0 = osb + (2 * wid + 2) * 25;
                    float* row1 = row0 + 625;
                    #pragma unroll
                    for (int k4 = 0; k4 < 3; k4++) {
                        const int t9 = 6 + k4;
                        #pragma unroll
                        for (int h = 0; h < 6; h++) {
                            if (k4 == 0 && h == 0 && ih != 0) continue;  // seam
                            float c0, c1;
                            unpack2(acc[t9 * 6 + h], c0, c1);
                            const int o4 = 2 * (i40 + h) + k4;
                            row0[o4] += c0;
                            row1[o4] += c1;
                        }
                    }
                }
                __syncthreads();  // scatter drained; safe to reload slabs / write out
            }
        }

        // write this co-half (coalesced along o3*25+o4)
        for (int i = tid; i < 20000; i += 384) {
            int co = i / 625, r = i - co * 625;
            out[(size_t)(b * 64 + co0 + co) * 390625 +
                o1 * 15625 + o2 * 625 + r] = out_s[i];
        }
        __syncthreads();  // before re-init of out_s for next half
    }
}

extern "C" void kernel_launch(void* const* d_in, const int* in_sizes, int n_in,
                              void* d_out, int out_size) {
    const float* x    = (const float*)d_in[0];
    const float* w    = (const float*)d_in[1];
    const float* bias = (const float*)d_in[2];
    float* out = (float*)d_out;

    (void)in_sizes; (void)n_in; (void)out_size;

    // idempotent, deterministic; required for >48KB dynamic smem
    cudaFuncSetAttribute(deconv4d_kernel,
                         cudaFuncAttributeMaxDynamicSharedMemorySize,
                         SMEM_FLOATS * sizeof(float));

    transpose_w_kernel<<<(NKW + 255) / 256, 256>>>(w);

    dim3 grid(625, 4);
    deconv4d_kernel<<<grid, 384, SMEM_FLOATS * sizeof(float)>>>(x, bias, out);
}

// round 14
// speedup vs baseline: 1.1061x; 1.1061x over previous
#include <cuda_runtime.h>

// 4D transposed conv, stride 2:
//   out[b,co,o1..o4] = bias[co] + sum_{ci,k1..k4 : o=2i+k} x[b,ci,i1..i4] * w[ci,co,k1..k4]
// Per (b,o1,o2) block: for each valid (k1,k2)->(i1,i2) combo,
//   GEMM C[(i3,i4),(co,k3,k4)] = sum_ci x[ci,i3,i4]*w[ci,co,k3,k4]   (fma.rn.f32x2)
//   scatter out_s[co][2*i3+k3][2*i4+k4] += C
// R5 tiling: warp w owns i3 row w (12 warps), lane -> co, thread = 12 i4
// (6 FFMA2 pairs) x 9 taps. THIS ROUND: taps split into 3 k3-groups (outer),
// ci inner -> accs 36 regs instead of 108, freeing registers for an explicit
// 1-ci-ahead double-buffered prefetch of x (3x LDS.128) and w (3x LDS.32),
// hiding all LDS latency under the 18 FFMA2s per ci. Each group scatters one
// o3 row (2*wid+g); BAR between g1 and g2 prevents the 2w+2 vs 2(w+1) race.

#define NKW (81 * 64 * 64)
__device__ float g_wT[NKW];  // [k1,k2,k3,k4][ci][co]

__global__ void transpose_w_kernel(const float* __restrict__ w) {
    int idx = blockIdx.x * blockDim.x + threadIdx.x;
    if (idx < NKW) {
        int kidx = idx >> 12;        // 0..80
        int cico = idx & 4095;       // ci*64+co
        g_wT[idx] = w[cico * 81 + kidx];
    }
}

// smem (floats): out_s[32*625]=20000, w_s[9*64*32]=18432,
//                x_s[64][12][16]=12288, pad 192 (ci=64 prefetch overrun)
#define WS_OFF 20000
#define XS_OFF 38432
#define SMEM_FLOATS 50912

typedef unsigned long long u64;

__device__ __forceinline__ void fma2(u64& d, u64 a, u64 b) {
    asm("fma.rn.f32x2 %0, %1, %2, %0;" : "+l"(d) : "l"(a), "l"(b));
}
__device__ __forceinline__ u64 pack2(float w) {
    u64 r;
    asm("mov.b64 %0, {%1, %1};" : "=l"(r) : "f"(w));
    return r;
}
__device__ __forceinline__ void unpack2(u64 v, float& lo, float& hi) {
    unsigned int l, h;
    asm("mov.b64 {%0, %1}, %2;" : "=r"(l), "=r"(h) : "l"(v));
    lo = __uint_as_float(l);
    hi = __uint_as_float(h);
}

__global__ __launch_bounds__(384, 1) void deconv4d_kernel(
    const float* __restrict__ x, const float* __restrict__ bias,
    float* __restrict__ out)
{
    extern __shared__ float smem[];
    float* out_s = smem;               // [32 co][25 o3][25 o4]
    float* w_s   = smem + WS_OFF;      // [t9=k3*3+k4][ci][co(32)]
    float* x_s   = smem + XS_OFF;      // [ci][i3][16] (12 used, pad for LDS.128)

    const int tid  = threadIdx.x;
    const int lane = tid & 31;         // -> co within half
    const int wid  = tid >> 5;         // -> i3 row (0..11)
    const int b  = blockIdx.y;
    const int o1 = blockIdx.x / 25;
    const int o2 = blockIdx.x % 25;

    // valid (k,i) pairs for dims 1 and 2
    int nk1 = 0, k1s[2], i1s[2];
    #pragma unroll
    for (int k = 0; k < 3; k++)
        if (k <= o1 && ((o1 - k) & 1) == 0 && ((o1 - k) >> 1) < 12) {
            k1s[nk1] = k; i1s[nk1] = (o1 - k) >> 1; nk1++;
        }
    int nk2 = 0, k2s[2], i2s[2];
    #pragma unroll
    for (int k = 0; k < 3; k++)
        if (k <= o2 && ((o2 - k) & 1) == 0 && ((o2 - k) >> 1) < 12) {
            k2s[nk2] = k; i2s[nk2] = (o2 - k) >> 1; nk2++;
        }

    for (int coh = 0; coh < 2; coh++) {
        const int co0 = coh * 32;

        // init accumulation buffer with bias
        for (int i = tid; i < 20000; i += 384)
            out_s[i] = bias[co0 + i / 625];
        __syncthreads();

        for (int c1 = 0; c1 < nk1; c1++) {
            for (int c2 = 0; c2 < nk2; c2++) {
                const int i1 = i1s[c1], i2 = i2s[c2];
                const int kbase = (k1s[c1] * 3 + k2s[c2]) * 9;

                // x slab [64 ci][12 i3][16 pad] as float2 (rows 12 floats)
                for (int t = tid; t < 4608; t += 384) {
                    int ci = t / 72, r = t - ci * 72;
                    int i3 = r / 6,  j = r - i3 * 6;
                    size_t sb = ((size_t)((b * 64 + ci) * 144 + i1 * 12 + i2)) * 72;
                    ((float2*)x_s)[ci * 96 + i3 * 8 + j] =
                        ((const float2*)x)[sb + i3 * 6 + j];
                }
                // w slab [9 taps][64 ci][32 co]
                for (int t = tid; t < 4608; t += 384) {
                    int c4 = t & 7, ci = (t >> 3) & 63, t9 = t >> 9;
                    ((float4*)w_s)[t] = *(const float4*)(g_wT +
                        (kbase + t9) * 4096 + ci * 64 + co0 + c4 * 4);
                }
                __syncthreads();

                const float* xb  = x_s + wid * 16;
                float* osb = out_s + lane * 625;

                // 3 k3-groups: accs 18 u64, explicit 1-ci-ahead prefetch
                #pragma unroll 1
                for (int g = 0; g < 3; g++) {
                    u64 acc[18];
                    #pragma unroll
                    for (int i = 0; i < 18; i++) acc[i] = 0ULL;

                    const float* wg = w_s + lane + g * 3 * 2048;

                    u64  xv[2][6];
                    float wf[2][3];
                    {   // prologue: load ci=0
                        const ulonglong2* xp = (const ulonglong2*)xb;
                        ulonglong2 p0 = xp[0], p1 = xp[1], p2 = xp[2];
                        xv[0][0] = p0.x; xv[0][1] = p0.y; xv[0][2] = p1.x;
                        xv[0][3] = p1.y; xv[0][4] = p2.x; xv[0][5] = p2.y;
                        wf[0][0] = wg[0]; wf[0][1] = wg[2048]; wf[0][2] = wg[4096];
                    }

                    #pragma unroll 2
                    for (int ci = 0; ci < 64; ci++) {
                        const int cur = ci & 1, nx = cur ^ 1;
                        // prefetch ci+1 (ci=63 reads the smem pad — discarded)
                        const ulonglong2* xp =
                            (const ulonglong2*)(xb + (ci + 1) * 192);
                        ulonglong2 p0 = xp[0], p1 = xp[1], p2 = xp[2];
                        xv[nx][0] = p0.x; xv[nx][1] = p0.y; xv[nx][2] = p1.x;
                        xv[nx][3] = p1.y; xv[nx][4] = p2.x; xv[nx][5] = p2.y;
                        const float* wn = wg + (ci + 1) * 32;
                        wf[nx][0] = wn[0]; wf[nx][1] = wn[2048]; wf[nx][2] = wn[4096];

                        #pragma unroll
                        for (int k4 = 0; k4 < 3; k4++) {
                            u64 w2 = pack2(wf[cur][k4]);
                            fma2(acc[k4 * 6 + 0], xv[cur][0], w2);
                            fma2(acc[k4 * 6 + 1], xv[cur][1], w2);
                            fma2(acc[k4 * 6 + 2], xv[cur][2], w2);
                            fma2(acc[k4 * 6 + 3], xv[cur][3], w2);
                            fma2(acc[k4 * 6 + 4], xv[cur][4], w2);
                            fma2(acc[k4 * 6 + 5], xv[cur][5], w2);
                        }
                    }

                    // scatter group g: one o3 row = 2*wid+g (conflict-free:
                    // rows distinct across warps within a group; g0 vs g1 rows
                    // never collide; g2 vs next warp's g0 guarded by BAR below)
                    {
                        float* row = osb + (2 * wid + g) * 25;
                        #pragma unroll
                        for (int k4 = 0; k4 < 3; k4++) {
                            #pragma unroll
                            for (int h = 0; h < 6; h++) {
                                float lo, hi;
                                unpack2(acc[k4 * 6 + h], lo, hi);
                                row[4 * h + k4]     += lo;  // o4 = 2*(2h)+k4
                                row[4 * h + 2 + k4] += hi;  // o4 = 2*(2h+1)+k4
                            }
                        }
                    }
                    if (g >= 1) __syncthreads();
                    // g==1 BAR: all g0/g1 row writes done before any g2 write
                    // g==2 BAR: scatter + slab reads done before next fill
                }
            }
        }

        // write this co-half (coalesced along o3*25+o4)
        for (int i = tid; i < 20000; i += 384) {
            int co = i / 625, r = i - co * 625;
            out[(size_t)(b * 64 + co0 + co) * 390625 +
                o1 * 15625 + o2 * 625 + r] = out_s[i];
        }
        __syncthreads();  // before re-init of out_s for next half
    }
}

extern "C" void kernel_launch(void* const* d_in, const int* in_sizes, int n_in,
                              void* d_out, int out_size) {
    const float* x    = (const float*)d_in[0];
    const float* w    = (const float*)d_in[1];
    const float* bias = (const float*)d_in[2];
    float* out = (float*)d_out;

    (void)in_sizes; (void)n_in; (void)out_size;

    // idempotent, deterministic; required for >48KB dynamic smem
    cudaFuncSetAttribute(deconv4d_kernel,
                         cudaFuncAttributeMaxDynamicSharedMemorySize,
                         SMEM_FLOATS * sizeof(float));

    transpose_w_kernel<<<(NKW + 255) / 256, 256>>>(w);

    dim3 grid(625, 4);
    deconv4d_kernel<<<grid, 384, SMEM_FLOATS * sizeof(float)>>>(x, bias, out);
}